// round 17
// baseline (speedup 1.0000x reference)
#include <cuda_runtime.h>
#include <cuda_fp16.h>
#include <mma.h>
#include <cstdint>
#include <cstddef>

using namespace nvcuda;

#define NN 100000
#define NE 1600000
#define D  128
#define SCAN_B 1024
#define NBLK ((NN + SCAN_B - 1) / SCAN_B)   // 98
#define NTILE ((NN + 127) / 128)            // 782

// Scratch (static device globals; no allocation allowed)
__device__ int    g_is64;
__device__ int    g_deg[NN];
__device__ int    g_chain[NBLK];   // chained-scan prefixes (-1 = not ready)
__device__ int    g_rowstart[NN];
__device__ int    g_cursor[NN];
__device__ int    g_csr[NE];
__device__ float  g_dinv[NN];
__device__ __half g_W1h[D * D];            // W1^T in fp16, [N=128][K=128]
__device__ __half g_HSh[(size_t)NN * D];   // fp16: UNSCALED (x @ W1)[u]
__device__ float  g_HS2[NN * 2];

// bit-cast helpers
__device__ __forceinline__ unsigned int h2_as_u32(__half2 h) {
    return *reinterpret_cast<unsigned int*>(&h);
}
__device__ __forceinline__ __half2 u32_as_h2(unsigned int u) {
    return *reinterpret_cast<__half2*>(&u);
}

// GEMM smem geometry: A/B staged as 128 rows x 136 halves (padded, ldm%8==0;
// 8-phase bank stagger), fp32 C reuses the same space afterwards.
#define APAD 136
#define SM_A_OFF 0
#define SM_B_OFF (128 * APAD * 2)                 // 34816
#define SM_GEMM_TOT (2 * 128 * APAD * 2)          // 69632 (>= 64KB C buffer)

// ---------------------------------------------------------------------------
// 0) zero degrees + reset chain + (block 0) probe edge dtype.
//    int64 -> all odd 32-bit words are 0 (high words of idx < 2^31).
// ---------------------------------------------------------------------------
__global__ void zero_probe_kernel(const int* __restrict__ raw) {
    const int i = blockIdx.x * blockDim.x + threadIdx.x;
    if (i < NN) g_deg[i] = 0;
    if (i < NBLK) g_chain[i] = -1;
    if (blockIdx.x == 0) {
        __shared__ int nz;
        if (threadIdx.x == 0) nz = 0;
        __syncthreads();
        const int idx = 2 * (threadIdx.x * 4096) + 1;   // < 2*NE
        if (raw[idx] != 0) atomicAdd(&nz, 1);
        __syncthreads();
        if (threadIdx.x == 0) g_is64 = (nz == 0) ? 1 : 0;
    }
}

// ----- side chain: deg -> fused scan -> fill -------------------------------
__global__ void deg_kernel(const int* __restrict__ raw) {
    const int e = blockIdx.x * blockDim.x + threadIdx.x;
    if (e >= NE) return;
    const int d = g_is64 ? raw[2 * (NE + e)] : raw[NE + e];
    atomicAdd(&g_deg[d], 1);
}

// Fused scan: block-level inclusive scan + deterministic chained prefix
// (98 blocks, all co-resident on 148 SMs -> spin is deadlock-free) +
// rowstart/cursor/dinv epilogue. Replaces scan1+scan2+scan3.
__global__ __launch_bounds__(SCAN_B) void scan_fused_kernel() {
    __shared__ int sh[SCAN_B];
    __shared__ int s_prefix;
    const int i = blockIdx.x * SCAN_B + threadIdx.x;
    const int dg = (i < NN) ? g_deg[i] : 0;
    sh[threadIdx.x] = dg;
    __syncthreads();
#pragma unroll
    for (int o = 1; o < SCAN_B; o <<= 1) {
        int t = (threadIdx.x >= o) ? sh[threadIdx.x - o] : 0;
        __syncthreads();
        sh[threadIdx.x] += t;
        __syncthreads();
    }
    if (threadIdx.x == 0) {
        int pre = 0;
        if (blockIdx.x > 0) {
            while ((pre = atomicAdd(&g_chain[blockIdx.x - 1], 0)) < 0) {}
        }
        s_prefix = pre;
        __threadfence();
        atomicExch(&g_chain[blockIdx.x], pre + sh[SCAN_B - 1]);
    }
    __syncthreads();
    if (i < NN) {
        const int excl = s_prefix + sh[threadIdx.x] - dg;
        g_rowstart[i] = excl;
        g_cursor[i]   = excl;
        g_dinv[i]     = rsqrtf((float)(dg + 1));
    }
}

__global__ void fill_kernel(const int* __restrict__ raw) {
    const int e = blockIdx.x * blockDim.x + threadIdx.x;
    if (e >= NE) return;
    int s, d;
    if (g_is64) { s = raw[2 * e]; d = raw[2 * (NE + e)]; }
    else        { s = raw[e];     d = raw[NE + e]; }
    const int p = atomicAdd(&g_cursor[d], 1);
    g_csr[p] = s;
}

// ---------------------------------------------------------------------------
// main 1a) W1^T -> fp16 (once, tiny): g_W1h[n][k] = W1[k][n]
// ---------------------------------------------------------------------------
__global__ void w1t_kernel(const float* __restrict__ W1) {
    const int i = blockIdx.x * blockDim.x + threadIdx.x;   // 16384
    if (i >= D * D) return;
    const int k = i >> 7, n = i & 127;
    g_W1h[n * 128 + k] = __float2half(W1[k * 128 + n]);    // coalesced read
}

// ---------------------------------------------------------------------------
// main 1b) wmma fp16 GEMM: HSh = fp16(X @ W1), 128x128x128 tile per block.
// ---------------------------------------------------------------------------
__global__ __launch_bounds__(256) void mma_gemm_kernel(const float* __restrict__ X) {
    extern __shared__ char smem[];
    __half* As = (__half*)(smem + SM_A_OFF);
    __half* Bs = (__half*)(smem + SM_B_OFF);
    const int tid = threadIdx.x;
    const int wid = tid >> 5;
    const int wm = wid & 1;          // 0..1  (64-row slab)
    const int wn = wid >> 1;         // 0..3  (32-col slab)
    const int m0 = blockIdx.x * 128;

    // ---- stage A: X fp32 -> fp16, rows padded to APAD halves ----
#pragma unroll
    for (int i = tid; i < 128 * 32; i += 256) {      // float4 chunks
        const int r = i >> 5;
        const int c4 = (i & 31) << 2;
        const int gr = m0 + r;
        float4 v = make_float4(0.f, 0.f, 0.f, 0.f);
        if (gr < NN) v = *(const float4*)(X + (size_t)gr * 128 + c4);
        const __half2 h0 = __floats2half2_rn(v.x, v.y);
        const __half2 h1 = __floats2half2_rn(v.z, v.w);
        *(uint2*)(As + r * APAD + c4) = make_uint2(h2_as_u32(h0), h2_as_u32(h1));
    }
    // ---- stage B: g_W1h rows -> padded smem ----
#pragma unroll
    for (int i = tid; i < 128 * 16; i += 256) {      // uint4 chunks (8 halves)
        const int r = i >> 4;
        const int c8 = (i & 15) << 3;
        *(uint4*)(Bs + r * APAD + c8) = *(const uint4*)(g_W1h + r * 128 + c8);
    }
    __syncthreads();

    // ---- wmma mainloop ----
    wmma::fragment<wmma::accumulator, 16, 16, 16, float> acc[4][2];
#pragma unroll
    for (int mi = 0; mi < 4; mi++)
#pragma unroll
        for (int ni = 0; ni < 2; ni++) wmma::fill_fragment(acc[mi][ni], 0.f);

#pragma unroll
    for (int kk = 0; kk < 8; kk++) {
        wmma::fragment<wmma::matrix_a, 16, 16, 16, __half, wmma::row_major> af[4];
        wmma::fragment<wmma::matrix_b, 16, 16, 16, __half, wmma::col_major> bf[2];
#pragma unroll
        for (int mi = 0; mi < 4; mi++)
            wmma::load_matrix_sync(af[mi], As + (wm * 64 + mi * 16) * APAD + kk * 16, APAD);
#pragma unroll
        for (int ni = 0; ni < 2; ni++)
            wmma::load_matrix_sync(bf[ni], Bs + (wn * 32 + ni * 16) * APAD + kk * 16, APAD);
#pragma unroll
        for (int mi = 0; mi < 4; mi++)
#pragma unroll
            for (int ni = 0; ni < 2; ni++)
                wmma::mma_sync(acc[mi][ni], af[mi], bf[ni], acc[mi][ni]);
    }
    __syncthreads();                 // done reading As/Bs; reuse as fp32 C

    float* Cs = (float*)smem;        // 128 x 128 fp32 = 64KB <= 68KB
#pragma unroll
    for (int mi = 0; mi < 4; mi++)
#pragma unroll
        for (int ni = 0; ni < 2; ni++)
            wmma::store_matrix_sync(Cs + (wm * 64 + mi * 16) * 128 + wn * 32 + ni * 16,
                                    acc[mi][ni], 128, wmma::mem_row_major);
    __syncthreads();

    // ---- fp32 C -> fp16 HS, coalesced ----
#pragma unroll
    for (int i = tid; i < 128 * 16; i += 256) {      // 8-float chunks
        const int r = i >> 4;
        const int c8 = (i & 15) << 3;
        const int gr = m0 + r;
        if (gr >= NN) continue;
        const float4 v0 = *(const float4*)(Cs + r * 128 + c8);
        const float4 v1 = *(const float4*)(Cs + r * 128 + c8 + 4);
        uint4 o;
        o.x = h2_as_u32(__floats2half2_rn(v0.x, v0.y));
        o.y = h2_as_u32(__floats2half2_rn(v0.z, v0.w));
        o.z = h2_as_u32(__floats2half2_rn(v1.x, v1.y));
        o.w = h2_as_u32(__floats2half2_rn(v1.z, v1.w));
        *(uint4*)(g_HSh + (size_t)gr * 128 + c8) = o;
    }
}

// ---------------------------------------------------------------------------
// 2) fused layer-1 aggregation (CSR gather over fp16 HS, fp32 accumulate,
//    dinv[src] folded in, 4-edge unroll for MLP) + ReLU + W2
// ---------------------------------------------------------------------------
__global__ __launch_bounds__(256) void gather_layer2_kernel(const float* __restrict__ b1,
                                                            const float* __restrict__ W2) {
    __shared__ float sW2[256];
    __shared__ float sb1[128];
    const int tid = threadIdx.x;
    if (tid < 256) sW2[tid] = W2[tid];
    if (tid < 128) sb1[tid] = b1[tid];
    __syncthreads();
    const int v = (blockIdx.x * blockDim.x + tid) >> 5;
    const int lane = tid & 31;
    if (v >= NN) return;

    const float dinv = g_dinv[v];

    uint2 sp = *(const uint2*)(g_HSh + (size_t)v * 128 + lane * 4);
    float2 l0 = __half22float2(u32_as_h2(sp.x));
    float2 l1 = __half22float2(u32_as_h2(sp.y));
    float a0 = dinv * l0.x, a1 = dinv * l0.y, a2 = dinv * l1.x, a3 = dinv * l1.y;

    const int start = g_rowstart[v];
    const int deg = g_deg[v];
    int j = 0;
    for (; j + 4 <= deg; j += 4) {
        const int s0 = g_csr[start + j];
        const int s1 = g_csr[start + j + 1];
        const int s2 = g_csr[start + j + 2];
        const int s3 = g_csr[start + j + 3];
        const float w0 = __ldg(&g_dinv[s0]);
        const float w1 = __ldg(&g_dinv[s1]);
        const float w2 = __ldg(&g_dinv[s2]);
        const float w3 = __ldg(&g_dinv[s3]);
        const uint2 p0 = *(const uint2*)(g_HSh + (size_t)s0 * 128 + lane * 4);
        const uint2 p1 = *(const uint2*)(g_HSh + (size_t)s1 * 128 + lane * 4);
        const uint2 p2 = *(const uint2*)(g_HSh + (size_t)s2 * 128 + lane * 4);
        const uint2 p3 = *(const uint2*)(g_HSh + (size_t)s3 * 128 + lane * 4);
        float2 q;
        q = __half22float2(u32_as_h2(p0.x)); a0 = fmaf(w0, q.x, a0); a1 = fmaf(w0, q.y, a1);
        q = __half22float2(u32_as_h2(p0.y)); a2 = fmaf(w0, q.x, a2); a3 = fmaf(w0, q.y, a3);
        q = __half22float2(u32_as_h2(p1.x)); a0 = fmaf(w1, q.x, a0); a1 = fmaf(w1, q.y, a1);
        q = __half22float2(u32_as_h2(p1.y)); a2 = fmaf(w1, q.x, a2); a3 = fmaf(w1, q.y, a3);
        q = __half22float2(u32_as_h2(p2.x)); a0 = fmaf(w2, q.x, a0); a1 = fmaf(w2, q.y, a1);
        q = __half22float2(u32_as_h2(p2.y)); a2 = fmaf(w2, q.x, a2); a3 = fmaf(w2, q.y, a3);
        q = __half22float2(u32_as_h2(p3.x)); a0 = fmaf(w3, q.x, a0); a1 = fmaf(w3, q.y, a1);
        q = __half22float2(u32_as_h2(p3.y)); a2 = fmaf(w3, q.x, a2); a3 = fmaf(w3, q.y, a3);
    }
    for (; j < deg; j++) {
        const int s0 = g_csr[start + j];
        const float w0 = __ldg(&g_dinv[s0]);
        const uint2 p0 = *(const uint2*)(g_HSh + (size_t)s0 * 128 + lane * 4);
        float2 q;
        q = __half22float2(u32_as_h2(p0.x)); a0 = fmaf(w0, q.x, a0); a1 = fmaf(w0, q.y, a1);
        q = __half22float2(u32_as_h2(p0.y)); a2 = fmaf(w0, q.x, a2); a3 = fmaf(w0, q.y, a3);
    }

    const float av[4] = {a0, a1, a2, a3};
    float p0 = 0.f, p1 = 0.f;
#pragma unroll
    for (int jj = 0; jj < 4; jj++) {
        const int k = lane * 4 + jj;
        const float x2 = fmaxf(fmaf(dinv, av[jj], sb1[k]), 0.f);
        p0 = fmaf(x2, sW2[k * 2 + 0], p0);
        p1 = fmaf(x2, sW2[k * 2 + 1], p1);
    }
#pragma unroll
    for (int o = 16; o > 0; o >>= 1) {
        p0 += __shfl_xor_sync(0xffffffffu, p0, o);
        p1 += __shfl_xor_sync(0xffffffffu, p1, o);
    }
    if (lane == 0) ((float2*)g_HS2)[v] = make_float2(dinv * p0, dinv * p1);
}

// ---------------------------------------------------------------------------
// 3) fused layer-2 aggregation + bias
// ---------------------------------------------------------------------------
__global__ __launch_bounds__(256) void gather2_final_kernel(const float* __restrict__ b2,
                                                            float* __restrict__ out) {
    const int v = (blockIdx.x * blockDim.x + threadIdx.x) >> 5;
    const int lane = threadIdx.x & 31;
    if (v >= NN) return;
    const int start = g_rowstart[v];
    const int deg = g_deg[v];
    float2 acc = (lane == 0) ? ((const float2*)g_HS2)[v] : make_float2(0.f, 0.f);
    for (int j = lane; j < deg; j += 32) {
        const float2 h = ((const float2*)g_HS2)[g_csr[start + j]];
        acc.x += h.x; acc.y += h.y;
    }
#pragma unroll
    for (int o = 16; o > 0; o >>= 1) {
        acc.x += __shfl_xor_sync(0xffffffffu, acc.x, o);
        acc.y += __shfl_xor_sync(0xffffffffu, acc.y, o);
    }
    if (lane == 0) {
        const float dinv = g_dinv[v];
        ((float2*)out)[v] = make_float2(fmaf(dinv, acc.x, b2[0]),
                                        fmaf(dinv, acc.y, b2[1]));
    }
}

// ---------------------------------------------------------------------------
extern "C" void kernel_launch(void* const* d_in, const int* in_sizes, int n_in,
                              void* d_out, int out_size) {
    const float* x  = (const float*)d_in[0];
    const int*   ei = (const int*)d_in[1];
    const float* W1 = (const float*)d_in[2];
    const float* b1 = (const float*)d_in[3];
    const float* W2 = (const float*)d_in[4];
    const float* b2 = (const float*)d_in[5];
    float* out = (float*)d_out;

    static cudaStream_t s_side = nullptr;
    static cudaEvent_t ev_fork = nullptr, ev_join = nullptr;
    if (s_side == nullptr) {
        cudaStreamCreateWithFlags(&s_side, cudaStreamNonBlocking);
        cudaEventCreateWithFlags(&ev_fork, cudaEventDisableTiming);
        cudaEventCreateWithFlags(&ev_join, cudaEventDisableTiming);
        cudaFuncSetAttribute(mma_gemm_kernel,
                             cudaFuncAttributeMaxDynamicSharedMemorySize, SM_GEMM_TOT);
    }

    const int T = 256;
    zero_probe_kernel<<<(NN + T - 1) / T, T>>>(ei);
    cudaEventRecord(ev_fork, 0);
    cudaStreamWaitEvent(s_side, ev_fork, 0);

    // side stream: CSR build chain (deg -> fused scan -> fill)
    deg_kernel      <<<(NE + T - 1) / T, T, 0, s_side>>>(ei);
    scan_fused_kernel<<<NBLK, SCAN_B, 0, s_side>>>();
    fill_kernel     <<<(NE + T - 1) / T, T, 0, s_side>>>(ei);
    cudaEventRecord(ev_join, s_side);

    // main stream: W1^T convert + wmma GEMM (hidden under side chain)
    w1t_kernel<<<(D * D + T - 1) / T, T>>>(W1);
    mma_gemm_kernel<<<NTILE, T, SM_GEMM_TOT>>>(x);

    cudaStreamWaitEvent(0, ev_join, 0);
    gather_layer2_kernel<<<(NN * 32 + T - 1) / T, T>>>(b1, W2);
    gather2_final_kernel<<<(NN * 32 + T - 1) / T, T>>>(b2, out);
}